// round 8
// baseline (speedup 1.0000x reference)
#include <cuda_runtime.h>
#include <cuda_fp16.h>
#include <cstdint>

// ---------------------------------------------------------------------------
// XORConv2d: out = conv_valid(x, 1-2W), x (32,128,64,64) f32, W (256,128,3,3)
// Implicit GEMM on mma.sync fp16/fp32. sm_103 plain target (no tcgen05).
// R8: x_to_nhwc prep kernel ELIMINATED — main CTA loads its NCHW fp32 patch
// directly (coalesced 1KB/channel), transposes+converts to fp16 in smem once.
// Mainloop identical to R7 (double-buffered A stages + register frag buffers).
// ---------------------------------------------------------------------------

#define BDIM   32
#define CIN    128
#define HH     64
#define WWID   64
#define COUT   256
#define HOUT   62
#define WOUT   62
#define PIX_PER_IMG (HOUT*WOUT)         // 3844

__device__ __half g_w[9 * COUT * CIN];   // (1-2W), [kp][co][cin]

static __device__ __forceinline__ uint32_t smem_u32(const void* p) {
    uint32_t a;
    asm("{ .reg .u64 t; cvta.to.shared.u64 t, %1; cvt.u32.u64 %0, t; }"
        : "=r"(a) : "l"(p));
    return a;
}

// ---------------------------------------------------------------------------
// Prep: W (co,cin,kh,kw) f32 {0,1} -> g_w[kp][co][cin] = 1-2W (fp16)
// ---------------------------------------------------------------------------
__global__ void w_prep(const float* __restrict__ W) {
    int idx = blockIdx.x * 256 + threadIdx.x;
    if (idx < COUT * CIN * 9) {
        int co  = idx / (CIN * 9);
        int r   = idx - co * (CIN * 9);
        int cin = r / 9;
        int kp  = r - cin * 9;
        g_w[(kp * COUT + co) * CIN + cin] = __float2half_rn(1.0f - 2.0f * W[idx]);
    }
}

// ---------------------------------------------------------------------------
// Main: CTA = 256 co x 124 pixels (image b, output rows r0, r0+1).
// Prologue: stage x rows r0..r0+3 (NCHW fp32, 128KB) into the A-stage smem
// area, transpose+convert -> 64KB fp16 [spatial][cin] swizzled patch.
// Then: A double-buffered over 9 kp, one barrier per kp, frag double-buffer.
// 16 warps: 4(M) x 4(N), warp tile 64x32. grid (31, 32), 512 threads.
//
// smem layout: [0,64K) patch | [64K, 64K+130K) A stages (2x64K) + 2K slack
//              (staging at stride 1040B/channel = 130K, used pre-A0 only)
// ---------------------------------------------------------------------------
#define PATCH_BYTES 65536
#define ASTAGE      65536
#define SMEM_BYTES  (PATCH_BYTES + 2*ASTAGE + 2048)

__global__ void __launch_bounds__(512, 1)
xorconv_main(const float* __restrict__ x, float* __restrict__ out) {
    extern __shared__ char smem[];
    const uint32_t sb = smem_u32(smem);
    const uint32_t PB = sb;                     // fp16 patch
    const uint32_t AB = sb + PATCH_BYTES;       // A stages (also fp32 staging)

    const int tid = threadIdx.x;
    const int l   = tid & 31;
    const int w   = tid >> 5;          // 0..15
    const int wm  = w & 3;             // M group (64 co)
    const int wn  = w >> 2;            // N group (32 pix)
    const int b   = blockIdx.y;
    const int r0  = blockIdx.x * 2;    // first output row (0..60)

    // ================= Prologue: x patch -> smem =================
    // Stage: channel c contributes rows r0..r0+3 = 256 consecutive floats
    // (1KB contiguous in NCHW). Staging stride 1040B per channel.
    {
        const int c = tid >> 2, q = tid & 3;   // c 0..127, quarter q
        const float* src = x + ((size_t)(b * CIN + c) * (HH * WWID) + r0 * WWID)
                             + q * 64;
        uint32_t dst = AB + (uint32_t)c * 1040u + (uint32_t)q * 256u;
#pragma unroll
        for (int i = 0; i < 16; i++)
            asm volatile("cp.async.cg.shared.global [%0], [%1], 16;"
                         :: "r"(dst + i * 16), "l"(src + i * 4));
        asm volatile("cp.async.commit_group;" ::: "memory");
        asm volatile("cp.async.wait_group 0;" ::: "memory");
    }
    __syncthreads();

    // Transpose+convert: staging [c][sp] fp32 -> patch [sp][c] fp16 swizzled.
    {
        const float* stg = (const float*)(smem + PATCH_BYTES);
        const int sp4 = (tid & 63) * 4;        // 4 spatial rows
        const int cb  = (tid >> 6) * 16;       // 16 channels
#pragma unroll
        for (int k = 0; k < 8; k++) {
            int c0 = cb + 2 * k;
            float4 v0 = *(const float4*)(stg + c0 * 260 + sp4);
            float4 v1 = *(const float4*)(stg + (c0 + 1) * 260 + sp4);
            int cc  = c0 >> 3;                 // 16B chunk within row
            int inb = (2 * c0) & 15;           // byte within chunk
            __half2 h0 = __floats2half2_rn(v0.x, v1.x);
            __half2 h1 = __floats2half2_rn(v0.y, v1.y);
            __half2 h2 = __floats2half2_rn(v0.z, v1.z);
            __half2 h3 = __floats2half2_rn(v0.w, v1.w);
            uint32_t hv[4] = {*(uint32_t*)&h0, *(uint32_t*)&h1,
                              *(uint32_t*)&h2, *(uint32_t*)&h3};
#pragma unroll
            for (int r = 0; r < 4; r++) {
                int sp = sp4 + r;
                uint32_t ad = (uint32_t)sp * 256u
                            + (uint32_t)((cc ^ (sp & 7)) * 16) + inb;
                *(uint32_t*)(smem + ad) = hv[r];
            }
        }
    }
    __syncthreads();   // patch complete; staging (A area) fully consumed

    // ================= Mainloop (identical to R7) =================
    const int c    = tid & 15;         // 16B chunk in a 256B row
    const int rgrp = tid >> 4;         // 32 groups; rows r = rgrp + 32*i

    auto load_A = [&](int s, int kp) {
        uint32_t dA = AB + s * ASTAGE;
        const __half* wp = g_w + kp * COUT * CIN;
#pragma unroll
        for (int i = 0; i < 8; i++) {
            int r = rgrp + 32 * i;
            uint32_t sw = (uint32_t)r * 256u + (uint32_t)((c ^ (r & 7)) * 16);
            asm volatile("cp.async.cg.shared.global [%0], [%1], 16;"
                         :: "r"(dA + sw), "l"(wp + r * CIN + c * 8));
        }
        asm volatile("cp.async.commit_group;" ::: "memory");
    };

    load_A(0, 0);

    const uint32_t selA = (uint32_t)(l >> 4);
    const uint32_t selB = (uint32_t)((l >> 3) & 1);
    const int rowA0 = wm * 64 + (l & 15);
    int pr0[2];
#pragma unroll
    for (int nb = 0; nb < 2; nb++) {
        int n = wn * 32 + (l & 7) + ((l >> 4) << 3) + nb * 16;
        if (n > 123) n = 123;
        pr0[nb] = (n / WOUT) * WWID + (n % WOUT);
    }

    float acc[4][4][4];
#pragma unroll
    for (int a = 0; a < 4; a++)
#pragma unroll
        for (int bb = 0; bb < 4; bb++)
#pragma unroll
            for (int e = 0; e < 4; e++) acc[a][bb][e] = 0.f;

    uint32_t afr[2][4][4], bfr[2][2][4];

    for (int kp = 0; kp < 9; kp++) {
        asm volatile("cp.async.wait_group 0;" ::: "memory");
        __syncthreads();
        if (kp < 8) load_A((kp + 1) & 1, kp + 1);   // overlaps compute below

        const uint32_t A = AB + (kp & 1) * ASTAGE;
        const int kh = kp / 3, kw = kp - 3 * kh;
        const int shift = kh * WWID + kw;
        uint32_t prow[2], pbase[2];
#pragma unroll
        for (int nb = 0; nb < 2; nb++) {
            prow[nb]  = (uint32_t)(pr0[nb] + shift);
            pbase[nb] = PB + prow[nb] * 256u;
        }

        auto load_frags = [&](int j, int p) {
#pragma unroll
            for (int fm = 0; fm < 4; fm++) {
                int r = rowA0 + fm * 16;
                uint32_t ch = ((uint32_t)(2 * j) + selA) ^ (uint32_t)(r & 7);
                uint32_t ad = A + (uint32_t)r * 256u + ch * 16u;
                asm volatile(
                    "ldmatrix.sync.aligned.m8n8.x4.shared.b16 {%0,%1,%2,%3}, [%4];"
                    : "=r"(afr[p][fm][0]), "=r"(afr[p][fm][1]),
                      "=r"(afr[p][fm][2]), "=r"(afr[p][fm][3])
                    : "r"(ad));
            }
#pragma unroll
            for (int nb = 0; nb < 2; nb++) {
                uint32_t ch = ((uint32_t)(2 * j) + selB) ^ (prow[nb] & 7u);
                uint32_t ad = pbase[nb] + ch * 16u;
                asm volatile(
                    "ldmatrix.sync.aligned.m8n8.x4.shared.b16 {%0,%1,%2,%3}, [%4];"
                    : "=r"(bfr[p][nb][0]), "=r"(bfr[p][nb][1]),
                      "=r"(bfr[p][nb][2]), "=r"(bfr[p][nb][3])
                    : "r"(ad));
            }
        };

        load_frags(0, 0);
#pragma unroll
        for (int j = 0; j < 8; j++) {            // K=128 in 8 x k16
            const int p = j & 1;
            if (j < 7) load_frags(j + 1, p ^ 1);
#pragma unroll
            for (int fm = 0; fm < 4; fm++)
#pragma unroll
                for (int nf = 0; nf < 4; nf++) {
                    asm volatile(
                        "mma.sync.aligned.m16n8k16.row.col.f32.f16.f16.f32 "
                        "{%0,%1,%2,%3}, {%4,%5,%6,%7}, {%8,%9}, {%0,%1,%2,%3};"
                        : "+f"(acc[fm][nf][0]), "+f"(acc[fm][nf][1]),
                          "+f"(acc[fm][nf][2]), "+f"(acc[fm][nf][3])
                        : "r"(afr[p][fm][0]), "r"(afr[p][fm][1]),
                          "r"(afr[p][fm][2]), "r"(afr[p][fm][3]),
                          "r"(bfr[p][nf >> 1][(nf & 1) * 2]),
                          "r"(bfr[p][nf >> 1][(nf & 1) * 2 + 1]));
                }
        }
    }

    // ----- epilogue: direct NCHW fp32 stores (skip pad pixels n>=124)
#pragma unroll
    for (int fm = 0; fm < 4; fm++) {
        int m = wm * 64 + fm * 16 + (l >> 2);
        size_t mb = (size_t)(b * COUT + m) * PIX_PER_IMG;
#pragma unroll
        for (int nf = 0; nf < 4; nf++) {
            int n0 = wn * 32 + nf * 8 + (l & 3) * 2;
#pragma unroll
            for (int e = 0; e < 2; e++) {
                int n = n0 + e;
                if (n < 124) {
                    int ho = r0 + (n >= WOUT ? 1 : 0);
                    int wo = n - (n >= WOUT ? WOUT : 0);
                    size_t idx = mb + (size_t)ho * WOUT + wo;
                    out[idx]                              = acc[fm][nf][e];
                    out[idx + (size_t)8 * PIX_PER_IMG]    = acc[fm][nf][2 + e];
                }
            }
        }
    }
}

// ---------------------------------------------------------------------------
extern "C" void kernel_launch(void* const* d_in, const int* in_sizes, int n_in,
                              void* d_out, int out_size) {
    const float* x = (const float*)d_in[0];
    const float* W = (const float*)d_in[1];
    float* out = (float*)d_out;

    w_prep<<<(COUT * CIN * 9 + 255) / 256, 256>>>(W);

    cudaFuncSetAttribute(xorconv_main,
                         cudaFuncAttributeMaxDynamicSharedMemorySize, SMEM_BYTES);
    dim3 gm(HOUT / 2, BDIM);   // 31 row-pairs x 32 images
    xorconv_main<<<gm, 512, SMEM_BYTES>>>(x, out);
}

// round 9
// speedup vs baseline: 1.8384x; 1.8384x over previous
#include <cuda_runtime.h>
#include <cuda_fp16.h>
#include <cstdint>

// ---------------------------------------------------------------------------
// XORConv2d: out = conv_valid(x, 1-2W), x (32,128,64,64) f32, W (256,128,3,3)
// Implicit GEMM on mma.sync fp16/fp32. sm_103 plain target (no tcgen05).
// R9: revert to R7 mainloop (measured best, ~87% tensor-pipe utilization);
// merge both prep jobs into ONE kernel launch; issue first ldmatrix frags
// before the A-prefetch cp.asyncs each kp.
// ---------------------------------------------------------------------------

#define BDIM   32
#define CIN    128
#define HH     64
#define WWID   64
#define COUT   256
#define HOUT   62
#define WOUT   62
#define PIX_PER_IMG (HOUT*WOUT)         // 3844

__device__ __half g_x[(size_t)BDIM * HH * WWID * CIN];   // NHWC fp16, 32 MB
__device__ __half g_w[9 * COUT * CIN];                   // (1-2W), [kp][co][cin]

static __device__ __forceinline__ uint32_t smem_u32(const void* p) {
    uint32_t a;
    asm("{ .reg .u64 t; cvta.to.shared.u64 t, %1; cvt.u32.u64 %0, t; }"
        : "=r"(a) : "l"(p));
    return a;
}

// ---------------------------------------------------------------------------
// Merged prep: blocks [0,8192) transpose x NCHW f32 -> NHWC f16 (full-sector
// packed half2 writes); blocks [8192, 8192+1152) build g_w = 1-2W.
// ---------------------------------------------------------------------------
#define XBLOCKS 8192
#define WBLOCKS ((COUT*CIN*9 + 255) / 256)    // 1152

__global__ void prep_all(const float* __restrict__ x,
                         const float* __restrict__ W) {
    if (blockIdx.x < XBLOCKS) {
        __shared__ float t[64][33];
        int bid = blockIdx.x;
        int bh  = bid & 2047;              // b*64 + h
        int rest = bid >> 11;              // 0..3
        int b  = bh >> 6, h = bh & 63;
        int c0 = (rest & 1) * 64;
        int w0 = (rest >> 1) * 32;
        int l  = threadIdx.x & 31, wy = threadIdx.x >> 5;   // 8 warps

        const float* src = x + ((size_t)(b * CIN + c0)) * (HH * WWID)
                             + h * WWID + w0;
#pragma unroll
        for (int i = 0; i < 8; i++)
            t[wy + 8 * i][l] = src[(size_t)(wy + 8 * i) * (HH * WWID) + l];
        __syncthreads();

#pragma unroll
        for (int i = 0; i < 4; i++) {
            int ww = wy + 8 * i;
            __half2 v = __floats2half2_rn(t[2 * l][ww], t[2 * l + 1][ww]);
            __half* drow = g_x + ((size_t)(bh * WWID) + w0 + ww) * CIN + c0;
            ((uint32_t*)drow)[l] = *(uint32_t*)&v;
        }
    } else {
        int idx = (blockIdx.x - XBLOCKS) * 256 + threadIdx.x;
        if (idx < COUT * CIN * 9) {
            int co  = idx / (CIN * 9);
            int r   = idx - co * (CIN * 9);
            int cin = r / 9;
            int kp  = r - cin * 9;
            g_w[(kp * COUT + co) * CIN + cin] =
                __float2half_rn(1.0f - 2.0f * W[idx]);
        }
    }
}

// ---------------------------------------------------------------------------
// Main: CTA = 256 co x 124 pixels (image b, output rows r0, r0+1).
// Patch = input rows r0..r0+3 (256 rows x 256B = 64KB), loaded once.
// A (weights) double-buffered over 9 kp, one barrier per kp; register
// double-buffered ldmatrix fragments. 16 warps: 4(M) x 4(N), warp 64x32.
// grid (31, 32), 512 threads.
// ---------------------------------------------------------------------------
#define ASTAGE 65536
#define SMEM_BYTES (2*65536 + 65536 + 2048)

__global__ void __launch_bounds__(512, 1)
xorconv_main(float* __restrict__ out) {
    extern __shared__ char smem[];
    const uint32_t sb = smem_u32(smem);
    const uint32_t PB = sb + 2 * ASTAGE;        // patch base

    const int tid = threadIdx.x;
    const int l   = tid & 31;
    const int w   = tid >> 5;          // 0..15
    const int wm  = w & 3;             // M group (64 co)
    const int wn  = w >> 2;            // N group (32 pix)
    const int b   = blockIdx.y;
    const int r0  = blockIdx.x * 2;    // first output row

    const int c    = tid & 15;         // 16B chunk in a 256B row
    const int rgrp = tid >> 4;         // 32 groups; rows r = rgrp + 32*i

    // Patch: 256 contiguous g_x rows starting at (b, r0, 0)
    {
        const __half* xsrc = g_x + ((size_t)(b * (HH * WWID) + r0 * WWID)) * CIN;
#pragma unroll
        for (int i = 0; i < 8; i++) {
            int r = rgrp + 32 * i;
            uint32_t sw = (uint32_t)r * 256u + (uint32_t)((c ^ (r & 7)) * 16);
            asm volatile("cp.async.cg.shared.global [%0], [%1], 16;"
                         :: "r"(PB + sw), "l"(xsrc + (size_t)r * CIN + c * 8));
        }
    }

    auto load_A = [&](int s, int kp) {
        uint32_t dA = sb + s * ASTAGE;
        const __half* wp = g_w + kp * COUT * CIN;
#pragma unroll
        for (int i = 0; i < 8; i++) {
            int r = rgrp + 32 * i;
            uint32_t sw = (uint32_t)r * 256u + (uint32_t)((c ^ (r & 7)) * 16);
            asm volatile("cp.async.cg.shared.global [%0], [%1], 16;"
                         :: "r"(dA + sw), "l"(wp + r * CIN + c * 8));
        }
        asm volatile("cp.async.commit_group;" ::: "memory");
    };

    load_A(0, 0);   // one group: patch + A0

    const uint32_t selA = (uint32_t)(l >> 4);
    const uint32_t selB = (uint32_t)((l >> 3) & 1);
    const int rowA0 = wm * 64 + (l & 15);
    int pr0[2];
#pragma unroll
    for (int nb = 0; nb < 2; nb++) {
        int n = wn * 32 + (l & 7) + ((l >> 4) << 3) + nb * 16;
        if (n > 123) n = 123;
        pr0[nb] = (n / WOUT) * WWID + (n % WOUT);
    }

    float acc[4][4][4];
#pragma unroll
    for (int a = 0; a < 4; a++)
#pragma unroll
        for (int bb = 0; bb < 4; bb++)
#pragma unroll
            for (int e = 0; e < 4; e++) acc[a][bb][e] = 0.f;

    uint32_t afr[2][4][4], bfr[2][2][4];

    for (int kp = 0; kp < 9; kp++) {
        asm volatile("cp.async.wait_group 0;" ::: "memory");
        __syncthreads();

        const uint32_t A = sb + (kp & 1) * ASTAGE;
        const int kh = kp / 3, kw = kp - 3 * kh;
        const int shift = kh * WWID + kw;
        uint32_t prow[2], pbase[2];
#pragma unroll
        for (int nb = 0; nb < 2; nb++) {
            prow[nb]  = (uint32_t)(pr0[nb] + shift);
            pbase[nb] = PB + prow[nb] * 256u;
        }

        auto load_frags = [&](int j, int p) {
#pragma unroll
            for (int fm = 0; fm < 4; fm++) {
                int r = rowA0 + fm * 16;
                uint32_t ch = ((uint32_t)(2 * j) + selA) ^ (uint32_t)(r & 7);
                uint32_t ad = A + (uint32_t)r * 256u + ch * 16u;
                asm volatile(
                    "ldmatrix.sync.aligned.m8n8.x4.shared.b16 {%0,%1,%2,%3}, [%4];"
                    : "=r"(afr[p][fm][0]), "=r"(afr[p][fm][1]),
                      "=r"(afr[p][fm][2]), "=r"(afr[p][fm][3])
                    : "r"(ad));
            }
#pragma unroll
            for (int nb = 0; nb < 2; nb++) {
                uint32_t ch = ((uint32_t)(2 * j) + selB) ^ (prow[nb] & 7u);
                uint32_t ad = pbase[nb] + ch * 16u;
                asm volatile(
                    "ldmatrix.sync.aligned.m8n8.x4.shared.b16 {%0,%1,%2,%3}, [%4];"
                    : "=r"(bfr[p][nb][0]), "=r"(bfr[p][nb][1]),
                      "=r"(bfr[p][nb][2]), "=r"(bfr[p][nb][3])
                    : "r"(ad));
            }
        };

        // First frags first (mma chain starts ~30cyc sooner), then prefetch A.
        load_frags(0, 0);
        if (kp < 8) load_A((kp + 1) & 1, kp + 1);   // overlaps compute below

#pragma unroll
        for (int j = 0; j < 8; j++) {            // K=128 in 8 x k16
            const int p = j & 1;
            if (j < 7) load_frags(j + 1, p ^ 1);
#pragma unroll
            for (int fm = 0; fm < 4; fm++)
#pragma unroll
                for (int nf = 0; nf < 4; nf++) {
                    asm volatile(
                        "mma.sync.aligned.m16n8k16.row.col.f32.f16.f16.f32 "
                        "{%0,%1,%2,%3}, {%4,%5,%6,%7}, {%8,%9}, {%0,%1,%2,%3};"
                        : "+f"(acc[fm][nf][0]), "+f"(acc[fm][nf][1]),
                          "+f"(acc[fm][nf][2]), "+f"(acc[fm][nf][3])
                        : "r"(afr[p][fm][0]), "r"(afr[p][fm][1]),
                          "r"(afr[p][fm][2]), "r"(afr[p][fm][3]),
                          "r"(bfr[p][nf >> 1][(nf & 1) * 2]),
                          "r"(bfr[p][nf >> 1][(nf & 1) * 2 + 1]));
                }
        }
    }

    // ----- epilogue: direct NCHW fp32 stores (skip pad pixels n>=124)
#pragma unroll
    for (int fm = 0; fm < 4; fm++) {
        int m = wm * 64 + fm * 16 + (l >> 2);
        size_t mb = (size_t)(b * COUT + m) * PIX_PER_IMG;
#pragma unroll
        for (int nf = 0; nf < 4; nf++) {
            int n0 = wn * 32 + nf * 8 + (l & 3) * 2;
#pragma unroll
            for (int e = 0; e < 2; e++) {
                int n = n0 + e;
                if (n < 124) {
                    int ho = r0 + (n >= WOUT ? 1 : 0);
                    int wo = n - (n >= WOUT ? WOUT : 0);
                    size_t idx = mb + (size_t)ho * WOUT + wo;
                    out[idx]                              = acc[fm][nf][e];
                    out[idx + (size_t)8 * PIX_PER_IMG]    = acc[fm][nf][2 + e];
                }
            }
        }
    }
}

// ---------------------------------------------------------------------------
extern "C" void kernel_launch(void* const* d_in, const int* in_sizes, int n_in,
                              void* d_out, int out_size) {
    const float* x = (const float*)d_in[0];
    const float* W = (const float*)d_in[1];
    float* out = (float*)d_out;

    prep_all<<<XBLOCKS + WBLOCKS, 256>>>(x, W);

    cudaFuncSetAttribute(xorconv_main,
                         cudaFuncAttributeMaxDynamicSharedMemorySize, SMEM_BYTES);
    dim3 gm(HOUT / 2, BDIM);   // 31 row-pairs x 32 images
    xorconv_main<<<gm, 512, SMEM_BYTES>>>(out);
}